// round 14
// baseline (speedup 1.0000x reference)
#include <cuda_runtime.h>
#include <cuda_bf16.h>

#define TH 512
#define MT 32
#define XAP 368   // XA row pitch (row-major), >=360, even, float4-aligned
#define XBP 264   // XB row pitch

// ---------------- device globals (no allocs allowed) ----------------
__device__ float g_scores[8 * 4096];
__device__ float g_probs[8 * 4096];
__device__ float g_cWt[256 * 360];    // combine W transposed [c][k], k padded to 360
__device__ float g_w1t[256 * 256];
__device__ float g_w2at[256 * 256];
__device__ float g_w2bt[256 * 256];
__device__ float g_vft[8 * 256 * 48]; // vf transposed per batch [b][g][a]

typedef unsigned long long ull;

__device__ __forceinline__ void upk2(ull v, float& a, float& b) {
    asm("mov.b64 {%0,%1}, %2;" : "=f"(a), "=f"(b) : "l"(v));
}
__device__ __forceinline__ ull fma2(ull a, ull b, ull c) {
    ull d;
    asm("fma.rn.f32x2 %0, %1, %2, %3;" : "=l"(d) : "l"(a), "l"(b), "l"(c));
    return d;
}

// ---------------- row-wise instance norm over 256 dims, row-major X, TH=512 ----------------
// r = tid>>4 (32 rows), part = tid&15 (16 parts x 16 contiguous floats)
__device__ __forceinline__ void rownorm_t(float* X, int P, int off, float* red1,
                                          float* red2, float* rowM, float* rowR,
                                          int tid) {
    int r = tid >> 4, part = tid & 15;
    float* base = X + r * P + off + part * 16;
    float s1 = 0.f, s2 = 0.f;
#pragma unroll
    for (int j = 0; j < 4; j++) {
        float4 v = *(float4*)(base + 4 * j);
        s1 += (v.x + v.y) + (v.z + v.w);
        s2 += (v.x * v.x + v.y * v.y) + (v.z * v.z + v.w * v.w);
    }
    red1[part * 33 + r] = s1;
    red2[part * 33 + r] = s2;
    __syncthreads();
    if (tid < 32) {
        float a = 0.f, bq = 0.f;
#pragma unroll
        for (int p = 0; p < 16; p++) {
            a += red1[p * 33 + tid];
            bq += red2[p * 33 + tid];
        }
        float m = a * (1.f / 256.f);
        float var = bq * (1.f / 256.f) - m * m;
        rowM[tid] = m;
        rowR[tid] = rsqrtf(var + 1e-5f);
    }
    __syncthreads();
    float m = rowM[r], rs = rowR[r];
#pragma unroll
    for (int j = 0; j < 4; j++) {
        float4 v = *(float4*)(base + 4 * j);
        v.x = (v.x - m) * rs;
        v.y = (v.y - m) * rs;
        v.z = (v.z - m) * rs;
        v.w = (v.w - m) * rs;
        *(float4*)(base + 4 * j) = v;
    }
    __syncthreads();
}

// ---------------- GEMM, K-pair packed f32x2, zero packing MOVs ----------------
// src row-major [32][srcP] (even pitch), dst row-major [32][dstP]+dstOff.
// Wt: prep-transposed global [256 c][4*KP4 k]. Smem tiles: 8 k as 4 k-pairs,
// layout [kp][256 c] of float2 (2048 floats per buffer), double-buffered.
// Thread map: tg=tid>>7 (rows 8tg..8tg+7), tc=tid&127 (cols tc, tc+128).
// acc = 16 ull, K-packed (even/odd k partials), halves summed in epilogue.
// act: 0=relu+bias, 1=leaky(0.01)+bias, 2=scale by invs[row]
__device__ __forceinline__ void gemm_kp(const float* __restrict__ src, int srcP,
                                        float* __restrict__ dst, int dstP, int dstOff,
                                        const float* __restrict__ Wt, int KP4,
                                        const float* __restrict__ bias,
                                        const float* __restrict__ invs,
                                        float* W0, float* W1, int Ktiles, int act,
                                        int tid) {
    int tg = tid >> 7;   // 0..3 -> rows 8tg..8tg+7
    int tc = tid & 127;  // cols tc, tc+128
    ull acc0[8], acc1[8];
#pragma unroll
    for (int i = 0; i < 8; i++) {
        acc0[i] = 0ull;
        acc1[i] = 0ull;
    }

    const float4* Wt4 = (const float4*)Wt;
    int sc = tid >> 1, sq = tid & 1;  // col 0..255, k-half 0..1
    float4 stg;

    // prologue: tile0 -> W0 (as k-pair float2s), prefetch tile1 -> regs
    stg = Wt4[sc * KP4 + sq];
    ((float2*)W0)[(sq * 2 + 0) * 256 + sc] = make_float2(stg.x, stg.y);
    ((float2*)W0)[(sq * 2 + 1) * 256 + sc] = make_float2(stg.z, stg.w);
    if (Ktiles > 1) stg = Wt4[sc * KP4 + 2 + sq];
    __syncthreads();

    for (int kt = 0; kt < Ktiles; kt++) {
        float* cur = (kt & 1) ? W1 : W0;
        float* nxt = (kt & 1) ? W0 : W1;
        if (kt + 1 < Ktiles) {
            ((float2*)nxt)[(sq * 2 + 0) * 256 + sc] = make_float2(stg.x, stg.y);
            ((float2*)nxt)[(sq * 2 + 1) * 256 + sc] = make_float2(stg.z, stg.w);
            if (kt + 2 < Ktiles) stg = Wt4[sc * KP4 + (kt + 2) * 2 + sq];
        }
        const float* xbase = src + (8 * tg) * srcP + kt * 8;
#pragma unroll
        for (int kp = 0; kp < 4; kp++) {
            ull w0 = *(const ull*)(cur + kp * 512 + 2 * tc);        // LDS.64
            ull w1 = *(const ull*)(cur + kp * 512 + 2 * tc + 256);  // LDS.64
#pragma unroll
            for (int i = 0; i < 8; i++) {
                ull x = *(const ull*)(xbase + i * srcP + 2 * kp);   // uniform LDS.64
                acc0[i] = fma2(x, w0, acc0[i]);
                acc1[i] = fma2(x, w1, acc1[i]);
            }
        }
        __syncthreads();
    }

    // epilogue: sum K-halves, bias/act, row-major stores (lanes contiguous)
#pragma unroll
    for (int c = 0; c < 2; c++) {
        int col = tc + 128 * c;
        float bb = (act != 2) ? __ldg(bias + col) : 0.f;
#pragma unroll
        for (int i = 0; i < 8; i++) {
            float lo, hi;
            upk2(c ? acc1[i] : acc0[i], lo, hi);
            float y = lo + hi;
            if (act == 2) {
                y *= invs[8 * tg + i];
            } else {
                y += bb;
                y = (act == 0) ? fmaxf(y, 0.f) : ((y > 0.f) ? y : 0.01f * y);
            }
            dst[(8 * tg + i) * dstP + dstOff + col] = y;
        }
    }
    __syncthreads();
}

// ---------------- prep: transpose weights / vf into device globals ----------------
__global__ void prep_kernel(const float* __restrict__ cW, const float* __restrict__ w1,
                            const float* __restrict__ w2a, const float* __restrict__ w2b,
                            const float* __restrict__ vf) {
    int i = blockIdx.x * 256 + threadIdx.x;
    if (i < 92160) {
        int c = i / 360, k = i - 360 * c;
        g_cWt[i] = (k < 356) ? cW[k * 256 + c] : 0.f;
        return;
    }
    i -= 92160;
    if (i < 65536) { g_w1t[i] = w1[((i & 255) << 8) + (i >> 8)]; return; }
    i -= 65536;
    if (i < 65536) { g_w2at[i] = w2a[((i & 255) << 8) + (i >> 8)]; return; }
    i -= 65536;
    if (i < 65536) { g_w2bt[i] = w2b[((i & 255) << 8) + (i >> 8)]; return; }
    i -= 65536;
    if (i < 98304) {
        int b = i / 12288, r = i - b * 12288;
        int g = r / 48, a = r - 48 * g;
        g_vft[i] = vf[b * 12288 + a * 256 + g];
    }
}

// ---------------- main fused kernel: one CTA = 32 subset rows of one batch ----------------
__global__ void __launch_bounds__(TH, 1)
fused_main(const float* __restrict__ vmask, const float* __restrict__ eoh_g,
           const int* __restrict__ subs, const float* __restrict__ cB,
           const float* __restrict__ b1, const float* __restrict__ b2a,
           const float* __restrict__ b2b, const float* __restrict__ sW,
           const float* __restrict__ sB) {
    extern __shared__ float sm[];
    float* XA = sm;                   // 32*368 = 11776
    float* XB = sm + 11776;           // 32*264 = 8448
    float* W0 = sm + 20224;           // 2048
    float* W1 = sm + 22272;           // 2048
    float* red1 = sm + 24320;         // 560 (16*33+32 padded)
    float* red2 = sm + 24880;         // 560
    float* red3 = sm + 25440;         // 560
    float* red4 = sm + 26000;         // 560
    float* rowM = sm + 26560;         // 32
    float* rowR = sm + 26592;         // 32
    float* invs = sm + 26624;         // 32
    float* maskv = sm + 26656;        // 48
    float* msq = sm + 26704;          // 48
    float* eoh = sm + 26752;          // 240
    float* swbuf = sm + 26992;        // 256 -> total 27248 floats (106.4 KB)

    int tid = threadIdx.x;
    int b = blockIdx.x >> 7;            // 128 tiles per batch
    int s0 = (blockIdx.x & 127) * MT;

    float* SRAW = W0;  // raw subset tile [32][49] = 1568 <= 4096 (W0+W1)
    float* SX = XB;    // stage-A X, row-major [32][48] (1536 <= 8448)

    // ---- loads ----
    if (tid < 48) {
        float m = vmask[b * 48 + tid];
        maskv[tid] = m;
        msq[tid] = m * m;
    }
    if (tid >= 256 && tid < 496) eoh[tid - 256] = eoh_g[b * 240 + (tid - 256)];
    if (tid < 256) swbuf[tid] = sW[tid];
    {
        const int* sb = subs + (b * 4096 + s0) * 48;
        for (int idx = tid; idx < 1536; idx += TH) {
            int r = idx / 48, a = idx - r * 48;
            SRAW[r * 49 + a] = (float)sb[idx];
        }
    }
    __syncthreads();

    // ---- counts (160 thr) + subset size (32 thr) ----
    if (tid < 160) {
        int r = tid / 5, e = tid - 5 * (tid / 5);
        float c = 0.f;
        for (int a = 0; a < 48; a++) c += SRAW[r * 49 + a] * eoh[a * 5 + e];
        red2[tid] = c;
    } else if (tid < 192) {
        int r = tid - 160;
        float sz = 0.f;
        for (int a = 0; a < 48; a++) sz += SRAW[r * 49 + a] * maskv[a];
        invs[r] = 1.f / (sz + 1e-4f);
    }
    __syncthreads();

    // ---- thermometer cols 0..99 + zero pad cols 356..359 ; SX = s*m^2 ----
    if (tid < 32) {
        int r = tid;
        float cnt[5];
#pragma unroll
        for (int e = 0; e < 5; e++) cnt[e] = red2[r * 5 + e];
        float* xr = XA + r * XAP;
#pragma unroll
        for (int e = 0; e < 5; e++)
            for (int j = 0; j < 20; j++)
                xr[e * 20 + j] = ((float)j < cnt[e]) ? 1.f : 0.f;
        xr[356] = 0.f; xr[357] = 0.f; xr[358] = 0.f; xr[359] = 0.f;
    }
    for (int idx = tid; idx < 1536; idx += TH) {
        int r = idx / 48, a = idx - r * 48;
        SX[r * 48 + a] = SRAW[r * 49 + a] * msq[a];
    }
    __syncthreads();

    // ---- stage A: meanfeat = (SX @ vf_t) * invs -> XA cols 100..355 ----
    gemm_kp(SX, 48, XA, XAP, 100, g_vft + b * 12288, 12, 0, invs, W0, W1, 6, 2, tid);

    rownorm_t(XA, XAP, 100, red1, red2, rowM, rowR, tid);               // subset_weighted_norm
    gemm_kp(XA, XAP, XB, XBP, 0, g_cWt, 90, cB, 0, W0, W1, 45, 0, tid); // combine + relu
    rownorm_t(XB, XBP, 0, red1, red2, rowM, rowR, tid);                 // norm_post_combine
    gemm_kp(XB, XBP, XA, XAP, 0, g_w1t, 64, b1, 0, W0, W1, 32, 0, tid); // l1 + relu
    gemm_kp(XA, XAP, XB, XBP, 0, g_w2at, 64, b2a, 0, W0, W1, 32, 1, tid); // l2a + leaky
    gemm_kp(XB, XBP, XA, XAP, 0, g_w2bt, 64, b2b, 0, W0, W1, 32, 0, tid); // l2b: leaky+relu==relu

    // ---- fused norm_pre_score + score head: score = rs*(Sxw - m*Sw) + b ----
    {
        int r = tid >> 4, part = tid & 15;
        const float* base = XA + r * XAP + part * 16;
        float s1 = 0.f, s2 = 0.f, sxw = 0.f, swp = 0.f;
#pragma unroll
        for (int j = 0; j < 4; j++) {
            float4 v = *(const float4*)(base + 4 * j);
            float4 w = *(const float4*)(swbuf + part * 16 + 4 * j);
            s1 += (v.x + v.y) + (v.z + v.w);
            s2 += (v.x * v.x + v.y * v.y) + (v.z * v.z + v.w * v.w);
            sxw += v.x * w.x + v.y * w.y + v.z * w.z + v.w * w.w;
            swp += (w.x + w.y) + (w.z + w.w);
        }
        red1[part * 33 + r] = s1;
        red2[part * 33 + r] = s2;
        red3[part * 33 + r] = sxw;
        red4[part * 33 + r] = swp;
        __syncthreads();
        if (tid < 32) {
            float a = 0.f, bq = 0.f, xw = 0.f, sw = 0.f;
#pragma unroll
            for (int p = 0; p < 16; p++) {
                a += red1[p * 33 + tid];
                bq += red2[p * 33 + tid];
                xw += red3[p * 33 + tid];
                sw += red4[p * 33 + tid];
            }
            float m = a * (1.f / 256.f);
            float var = bq * (1.f / 256.f) - m * m;
            float rs = rsqrtf(var + 1e-5f);
            g_scores[b * 4096 + s0 + tid] = rs * (xw - m * sw) + __ldg(sB);
        }
    }
}

// ---------------- per-batch softmax over 4096 scores ----------------
__global__ void softmax_kernel(float* __restrict__ probs_out) {
    __shared__ float sbuf[32];
    __shared__ float sval;
    int b = blockIdx.x, t = threadIdx.x, lane = t & 31, wid = t >> 5;
    const float* sc = g_scores + b * 4096;
    float v0 = sc[t], v1 = sc[t + 1024], v2 = sc[t + 2048], v3 = sc[t + 3072];
    float mx = fmaxf(fmaxf(v0, v1), fmaxf(v2, v3));
#pragma unroll
    for (int o = 16; o; o >>= 1) mx = fmaxf(mx, __shfl_xor_sync(0xffffffffu, mx, o));
    if (lane == 0) sbuf[wid] = mx;
    __syncthreads();
    if (t < 32) {
        float m = sbuf[t];
#pragma unroll
        for (int o = 16; o; o >>= 1) m = fmaxf(m, __shfl_xor_sync(0xffffffffu, m, o));
        if (t == 0) sval = m;
    }
    __syncthreads();
    mx = sval;
    float e0 = expf(v0 - mx), e1 = expf(v1 - mx), e2 = expf(v2 - mx), e3 = expf(v3 - mx);
    float sum = e0 + e1 + e2 + e3;
#pragma unroll
    for (int o = 16; o; o >>= 1) sum += __shfl_xor_sync(0xffffffffu, sum, o);
    __syncthreads();
    if (lane == 0) sbuf[wid] = sum;
    __syncthreads();
    if (t < 32) {
        float s = sbuf[t];
#pragma unroll
        for (int o = 16; o; o >>= 1) s += __shfl_xor_sync(0xffffffffu, s, o);
        if (t == 0) sval = s;
    }
    __syncthreads();
    float inv = 1.f / sval;
    float p0 = e0 * inv, p1 = e1 * inv, p2 = e2 * inv, p3 = e3 * inv;
    probs_out[b * 4096 + t] = p0;
    probs_out[b * 4096 + t + 1024] = p1;
    probs_out[b * 4096 + t + 2048] = p2;
    probs_out[b * 4096 + t + 3072] = p3;
    g_probs[b * 4096 + t] = p0;
    g_probs[b * 4096 + t + 1024] = p1;
    g_probs[b * 4096 + t + 2048] = p2;
    g_probs[b * 4096 + t + 3072] = p3;
}

// ---------------- zero + scatter into spectral bins ----------------
__global__ void zero_kernel(float* __restrict__ p, int n) {
    int idx = blockIdx.x * blockDim.x + threadIdx.x;
    if (idx < n) p[idx] = 0.f;
}

__global__ void scatter_kernel(const int* __restrict__ midx,
                               const float* __restrict__ inten,
                               float* __restrict__ spect) {
    int idx = blockIdx.x * blockDim.x + threadIdx.x;
    if (idx >= 8 * 4096 * 32) return;
    int b = idx >> 17;
    int s = (idx >> 5) & 4095;
    float w = inten[idx] * g_probs[b * 4096 + s];
    atomicAdd(spect + b * 65536 + midx[idx], w);
}

// ---------------- launch ----------------
extern "C" void kernel_launch(void* const* d_in, const int* in_sizes, int n_in,
                              void* d_out, int out_size) {
    const float* vf    = (const float*)d_in[0];
    const float* vmask = (const float*)d_in[1];
    const float* eoh   = (const float*)d_in[2];
    const int*   subs  = (const int*)d_in[4];
    const int*   midx  = (const int*)d_in[6];
    const float* inten = (const float*)d_in[7];
    const float* cW    = (const float*)d_in[8];
    const float* cB    = (const float*)d_in[9];
    const float* w1    = (const float*)d_in[10];
    const float* b1    = (const float*)d_in[11];
    const float* w2a   = (const float*)d_in[12];
    const float* b2a   = (const float*)d_in[13];
    const float* w2b   = (const float*)d_in[14];
    const float* b2b   = (const float*)d_in[15];
    const float* sW    = (const float*)d_in[16];
    const float* sB    = (const float*)d_in[17];
    float* out = (float*)d_out;

    int pOff = out_size - 8 * 4096;  // spect first, probs second
    size_t smem = (size_t)27248 * sizeof(float);
    cudaFuncSetAttribute(fused_main, cudaFuncAttributeMaxDynamicSharedMemorySize,
                         (int)smem);

    prep_kernel<<<1512, 256>>>(cW, w1, w2a, w2b, vf);
    zero_kernel<<<(pOff + 511) / 512, 512>>>(out, pOff);
    fused_main<<<1024, TH, smem>>>(vmask, eoh, subs, cB, b1, b2a, b2b, sW, sB);
    softmax_kernel<<<8, 1024>>>(out + pOff);
    scatter_kernel<<<2048, 512>>>(midx, inten, out);
}

// round 16
// speedup vs baseline: 1.9340x; 1.9340x over previous
#include <cuda_runtime.h>
#include <cuda_bf16.h>

#define TH 256
#define MT 32
#define PITCH 36    // 32 + 4: conflict-free, 144B col stride (16B aligned)
#define SUBP 49     // raw subset tile stride (odd -> conflict-free)

// ---------------- device globals (no allocs allowed) ----------------
__device__ float g_scores[8 * 4096];
__device__ float g_probs[8 * 4096];

typedef unsigned long long ull;

// ---------------- f32x2 helpers (sm_103a packed fp32 FMA) ----------------
__device__ __forceinline__ ull pk2(float a, float b) {
    ull r;
    asm("mov.b64 %0, {%1,%2};" : "=l"(r) : "f"(a), "f"(b));
    return r;
}
__device__ __forceinline__ void upk2(ull v, float& a, float& b) {
    asm("mov.b64 {%0,%1}, %2;" : "=f"(a), "=f"(b) : "l"(v));
}
__device__ __forceinline__ ull fma2(ull a, ull b, ull c) {
    ull d;
    asm("fma.rn.f32x2 %0, %1, %2, %3;" : "=l"(d) : "l"(a), "l"(b), "l"(c));
    return d;
}

// ---------------- row-wise instance norm over 256 dims, 32 rows ----------------
// X layout: X[k*PITCH + r], k in [0,256), r in [0,32)
__device__ __forceinline__ void rownorm(float* X, float* red1, float* red2,
                                        float* rowM, float* rowR, int tid) {
    int r = tid & 31, part = tid >> 5;  // 8 parts x 32 cols
    float s1 = 0.f, s2 = 0.f;
    const float* base = X + (part * 32) * PITCH + r;
#pragma unroll
    for (int g = 0; g < 32; g++) {
        float v = base[g * PITCH];
        s1 += v;
        s2 += v * v;
    }
    red1[part * 32 + r] = s1;
    red2[part * 32 + r] = s2;
    __syncthreads();
    if (tid < 32) {
        float a = 0.f, bq = 0.f;
#pragma unroll
        for (int p = 0; p < 8; p++) {
            a += red1[p * 32 + tid];
            bq += red2[p * 32 + tid];
        }
        float m = a * (1.f / 256.f);
        float var = bq * (1.f / 256.f) - m * m;
        rowM[tid] = m;
        rowR[tid] = rsqrtf(var + 1e-5f);
    }
    __syncthreads();
#pragma unroll
    for (int i = 0; i < 32; i++) {
        int c = (tid >> 5) + i * 8, rr = tid & 31;
        float* p = X + c * PITCH + rr;
        *p = (*p - rowM[rr]) * rowR[rr];
    }
    __syncthreads();
}

// ---------------- tiled GEMM: Y[r][c] = act( sum_k X[k][r]*W[k][c] + b[c] ) ----------------
// src/dst col-major (PITCH); dst MAY ALIAS src (all reads complete before the
// epilogue stores: accumulation is register-resident, last tile ends with a
// barrier). W streamed coalesced from global [k][256], 8-row tiles,
// double-buffered. Thread map: tr=tid>>6 (rows 8tr..8tr+7), tc=tid&63.
// acc packed along ROW pairs -> X via uniform LDS.128 (reg-pair aliasing, no
// MOV), W scalar LDS.32 + dup.
// act: 0=relu+bias, 1=leaky(0.01)+bias, 2=scale by invs[row] (no bias/act)
__device__ __forceinline__ void mlp_gemm(const float* src, float* dst,
                                         const float* __restrict__ Wg,
                                         const float* __restrict__ bias,
                                         const float* __restrict__ invs,
                                         float* W0, float* W1, int Krows,
                                         int Ktiles, int act, int tid) {
    int tr = tid >> 6;  // 0..3
    int tc = tid & 63;
    ull acc[4][4];
#pragma unroll
    for (int i = 0; i < 4; i++)
#pragma unroll
        for (int c = 0; c < 4; c++) acc[i][c] = 0ull;

    const float4* W4 = (const float4*)Wg;
    float4 stg[2];

    // prologue: tile0 -> W0, prefetch tile1 -> regs
#pragma unroll
    for (int i = 0; i < 2; i++) {
        int f4i = tid + TH * i;
        int row = f4i >> 6;
        stg[i] = make_float4(0.f, 0.f, 0.f, 0.f);
        if (row < Krows) stg[i] = W4[row * 64 + (f4i & 63)];
    }
#pragma unroll
    for (int i = 0; i < 2; i++) ((float4*)W0)[tid + TH * i] = stg[i];
    if (Ktiles > 1) {
#pragma unroll
        for (int i = 0; i < 2; i++) {
            int f4i = tid + TH * i;
            int row = (f4i >> 6) + 8;
            stg[i] = make_float4(0.f, 0.f, 0.f, 0.f);
            if (row < Krows) stg[i] = W4[row * 64 + (f4i & 63)];
        }
    }
    __syncthreads();

    for (int kt = 0; kt < Ktiles; kt++) {
        float* cur = (kt & 1) ? W1 : W0;
        float* nxt = (kt & 1) ? W0 : W1;
        if (kt + 1 < Ktiles) {
#pragma unroll
            for (int i = 0; i < 2; i++) ((float4*)nxt)[tid + TH * i] = stg[i];
            if (kt + 2 < Ktiles) {
#pragma unroll
                for (int i = 0; i < 2; i++) {
                    int f4i = tid + TH * i;
                    int row = (f4i >> 6) + (kt + 2) * 8;
                    stg[i] = make_float4(0.f, 0.f, 0.f, 0.f);
                    if (row < Krows) stg[i] = W4[row * 64 + (f4i & 63)];
                }
            }
        }
        const float* xbase = src + (kt * 8) * PITCH + 8 * tr;
#pragma unroll
        for (int k = 0; k < 8; k++) {
            float4 xa = *(const float4*)(xbase + k * PITCH);      // uniform
            float4 xb = *(const float4*)(xbase + k * PITCH + 4);  // uniform
            ull xp0 = pk2(xa.x, xa.y);
            ull xp1 = pk2(xa.z, xa.w);
            ull xp2 = pk2(xb.x, xb.y);
            ull xp3 = pk2(xb.z, xb.w);
            const float* wr = cur + k * 256 + tc;
#pragma unroll
            for (int c = 0; c < 4; c++) {
                float w = wr[64 * c];
                ull wd = pk2(w, w);
                acc[0][c] = fma2(xp0, wd, acc[0][c]);
                acc[1][c] = fma2(xp1, wd, acc[1][c]);
                acc[2][c] = fma2(xp2, wd, acc[2][c]);
                acc[3][c] = fma2(xp3, wd, acc[3][c]);
            }
        }
        __syncthreads();
    }

    // epilogue (all reads done; safe even if dst aliases src)
#pragma unroll
    for (int c = 0; c < 4; c++) {
        int col = tc + 64 * c;
        float y[8];
        if (act == 2) {
#pragma unroll
            for (int rp = 0; rp < 4; rp++) {
                float lo, hi;
                upk2(acc[rp][c], lo, hi);
                y[2 * rp] = lo * invs[8 * tr + 2 * rp];
                y[2 * rp + 1] = hi * invs[8 * tr + 2 * rp + 1];
            }
        } else {
            float bb = __ldg(bias + col);
#pragma unroll
            for (int rp = 0; rp < 4; rp++) {
                float lo, hi;
                upk2(acc[rp][c], lo, hi);
                lo += bb;
                hi += bb;
                if (act == 0) {
                    lo = fmaxf(lo, 0.f);
                    hi = fmaxf(hi, 0.f);
                } else {
                    lo = (lo > 0.f) ? lo : 0.01f * lo;
                    hi = (hi > 0.f) ? hi : 0.01f * hi;
                }
                y[2 * rp] = lo;
                y[2 * rp + 1] = hi;
            }
        }
        float* dcol = dst + col * PITCH + 8 * tr;
        *(float4*)dcol = make_float4(y[0], y[1], y[2], y[3]);
        *(float4*)(dcol + 4) = make_float4(y[4], y[5], y[6], y[7]);
    }
    __syncthreads();
}

// ---------------- main fused kernel: one CTA = 32 subset rows of one batch ----------------
// Single activation buffer X (360 cols x PITCH), all GEMMs in-place -> 71 KB smem, occ 3.
__global__ void __launch_bounds__(TH, 3)
fused_main(const float* __restrict__ vf, const float* __restrict__ vmask,
           const float* __restrict__ eoh_g, const int* __restrict__ subs,
           const float* __restrict__ cW, const float* __restrict__ cB,
           const float* __restrict__ w1, const float* __restrict__ b1,
           const float* __restrict__ w2a, const float* __restrict__ b2a,
           const float* __restrict__ w2b, const float* __restrict__ b2b,
           const float* __restrict__ sW, const float* __restrict__ sB) {
    extern __shared__ float sm[];
    float* X = sm;                    // 360*36 = 12960 floats
    float* W0 = sm + 12960;           // 2048
    float* W1 = sm + 15008;           // 2048
    float* red1 = sm + 17056;         // 256
    float* red2 = sm + 17312;         // 256
    float* rowM = sm + 17568;         // 32
    float* rowR = sm + 17600;         // 32
    float* invs = sm + 17632;         // 32
    float* maskv = sm + 17664;        // 48
    float* eoh = sm + 17712;          // 240
    float* swbuf = sm + 17952;        // 256 -> total 18208 floats (72.8 KB)

    int tid = threadIdx.x;
    int b = blockIdx.x >> 7;           // 128 tiles per batch
    int s0 = (blockIdx.x & 127) * MT;

    float* SRAW = W0;  // alias: raw subset tile [32][SUBP] = 1568 <= 2048

    // ---- loads: raw subsets, mask, element one-hot, score weights ----
    for (int idx = tid; idx < MT * 48; idx += TH) {
        int r = idx / 48, a = idx - r * 48;
        SRAW[r * SUBP + a] = (float)subs[(b * 4096 + s0) * 48 + idx];
    }
    if (tid < 48) maskv[tid] = vmask[b * 48 + tid];
    if (tid < 240) eoh[tid] = eoh_g[b * 240 + tid];
    swbuf[tid] = sW[tid];
    __syncthreads();

    // ---- counts (160 thr), subset size (32 thr) ----
    if (tid < 160) {
        int r = tid / 5, e = tid - 5 * (tid / 5);
        float c = 0.f;
        for (int a = 0; a < 48; a++) c += SRAW[r * SUBP + a] * eoh[a * 5 + e];
        red2[tid] = c;
    } else if (tid < 192) {
        int r = tid - 160;
        float sz = 0.f;
        for (int a = 0; a < 48; a++) sz += SRAW[r * SUBP + a] * maskv[a];
        invs[r] = 1.f / (sz + 1e-4f);
    }
    __syncthreads();

    // ---- thermometer cols 0..99 ; SX = (s*m^2) k-major into X cols 308..355 ;
    //      zero K-pad cols 356..359 ----
    if (tid < 32) {
        int r = tid;
        float cnt[5];
#pragma unroll
        for (int e = 0; e < 5; e++) cnt[e] = red2[r * 5 + e];
#pragma unroll
        for (int e = 0; e < 5; e++)
            for (int j = 0; j < 20; j++)
                X[(e * 20 + j) * PITCH + r] = ((float)j < cnt[e]) ? 1.f : 0.f;
    }
    for (int idx = tid; idx < 48 * 32; idx += TH) {
        int a = idx >> 5, r = idx & 31;
        float m = maskv[a];
        X[(308 + a) * PITCH + r] = SRAW[r * SUBP + a] * m * m;
    }
    if (tid >= 128 && tid < 256) {  // zero K-pad cols 356..359
        int rr = (tid - 128) & 31, col = 356 + ((tid - 128) >> 5);
        X[col * PITCH + rr] = 0.f;
    }
    __syncthreads();

    // ---- stage A as GEMM: meanfeat = (SX^T @ vf_b) * invs -> X cols 100..355 ----
    // (src cols 308..355 are re-read fully before the epilogue overwrites them)
    mlp_gemm(X + 308 * PITCH, X + 100 * PITCH, vf + b * 48 * 256, 0, invs, W0, W1,
             48, 6, 2, tid);

    rownorm(X + 100 * PITCH, red1, red2, rowM, rowR, tid);          // subset_weighted_norm
    mlp_gemm(X, X, cW, cB, 0, W0, W1, 356, 45, 0, tid);             // combine + relu (in-place)
    rownorm(X, red1, red2, rowM, rowR, tid);                        // norm_post_combine
    mlp_gemm(X, X, w1, b1, 0, W0, W1, 256, 32, 0, tid);             // l1 + relu
    mlp_gemm(X, X, w2a, b2a, 0, W0, W1, 256, 32, 1, tid);           // l2a + leaky
    mlp_gemm(X, X, w2b, b2b, 0, W0, W1, 256, 32, 0, tid);           // l2b: leaky+relu == relu

    // ---- fused norm_pre_score + score head: score = rs*(Sxw - m*Sw) + b ----
    {
        float* red3 = W0;        // W tiles free now
        float* red4 = W0 + 256;
        int r = tid & 31, part = tid >> 5;
        const float* base = X + (part * 32) * PITCH + r;
        float s1 = 0.f, s2 = 0.f, sxw = 0.f, swp = 0.f;
#pragma unroll
        for (int g = 0; g < 32; g++) {
            float v = base[g * PITCH];
            float w = swbuf[part * 32 + g];
            s1 += v;
            s2 += v * v;
            sxw += v * w;
            swp += w;
        }
        red1[part * 32 + r] = s1;
        red2[part * 32 + r] = s2;
        red3[part * 32 + r] = sxw;
        red4[part * 32 + r] = swp;
        __syncthreads();
        if (tid < 32) {
            float a = 0.f, bq = 0.f, xw = 0.f, sw = 0.f;
#pragma unroll
            for (int p = 0; p < 8; p++) {
                a += red1[p * 32 + tid];
                bq += red2[p * 32 + tid];
                xw += red3[p * 32 + tid];
                sw += red4[p * 32 + tid];
            }
            float m = a * (1.f / 256.f);
            float var = bq * (1.f / 256.f) - m * m;
            float rs = rsqrtf(var + 1e-5f);
            g_scores[b * 4096 + s0 + tid] = rs * (xw - m * sw) + __ldg(sB);
        }
    }
}

// ---------------- per-batch softmax over 4096 scores ----------------
__global__ void softmax_kernel(float* __restrict__ probs_out) {
    __shared__ float sbuf[32];
    __shared__ float sval;
    int b = blockIdx.x, t = threadIdx.x, lane = t & 31, wid = t >> 5;
    const float* sc = g_scores + b * 4096;
    float v0 = sc[t], v1 = sc[t + 1024], v2 = sc[t + 2048], v3 = sc[t + 3072];
    float mx = fmaxf(fmaxf(v0, v1), fmaxf(v2, v3));
#pragma unroll
    for (int o = 16; o; o >>= 1) mx = fmaxf(mx, __shfl_xor_sync(0xffffffffu, mx, o));
    if (lane == 0) sbuf[wid] = mx;
    __syncthreads();
    if (t < 32) {
        float m = sbuf[t];
#pragma unroll
        for (int o = 16; o; o >>= 1) m = fmaxf(m, __shfl_xor_sync(0xffffffffu, m, o));
        if (t == 0) sval = m;
    }
    __syncthreads();
    mx = sval;
    float e0 = expf(v0 - mx), e1 = expf(v1 - mx), e2 = expf(v2 - mx), e3 = expf(v3 - mx);
    float sum = e0 + e1 + e2 + e3;
#pragma unroll
    for (int o = 16; o; o >>= 1) sum += __shfl_xor_sync(0xffffffffu, sum, o);
    __syncthreads();
    if (lane == 0) sbuf[wid] = sum;
    __syncthreads();
    if (t < 32) {
        float s = sbuf[t];
#pragma unroll
        for (int o = 16; o; o >>= 1) s += __shfl_xor_sync(0xffffffffu, s, o);
        if (t == 0) sval = s;
    }
    __syncthreads();
    float inv = 1.f / sval;
    float p0 = e0 * inv, p1 = e1 * inv, p2 = e2 * inv, p3 = e3 * inv;
    probs_out[b * 4096 + t] = p0;
    probs_out[b * 4096 + t + 1024] = p1;
    probs_out[b * 4096 + t + 2048] = p2;
    probs_out[b * 4096 + t + 3072] = p3;
    g_probs[b * 4096 + t] = p0;
    g_probs[b * 4096 + t + 1024] = p1;
    g_probs[b * 4096 + t + 2048] = p2;
    g_probs[b * 4096 + t + 3072] = p3;
}

// ---------------- zero + scatter into spectral bins ----------------
__global__ void zero_kernel(float* __restrict__ p, int n) {
    int idx = blockIdx.x * blockDim.x + threadIdx.x;
    if (idx < n) p[idx] = 0.f;
}

__global__ void scatter_kernel(const int* __restrict__ midx,
                               const float* __restrict__ inten,
                               float* __restrict__ spect) {
    int idx = blockIdx.x * blockDim.x + threadIdx.x;
    if (idx >= 8 * 4096 * 32) return;
    int b = idx >> 17;              // 4096*32 = 131072
    int s = (idx >> 5) & 4095;
    float w = inten[idx] * g_probs[b * 4096 + s];
    atomicAdd(spect + b * 65536 + midx[idx], w);
}

// ---------------- launch ----------------
extern "C" void kernel_launch(void* const* d_in, const int* in_sizes, int n_in,
                              void* d_out, int out_size) {
    const float* vf    = (const float*)d_in[0];
    const float* vmask = (const float*)d_in[1];
    const float* eoh   = (const float*)d_in[2];
    const int*   subs  = (const int*)d_in[4];
    const int*   midx  = (const int*)d_in[6];
    const float* inten = (const float*)d_in[7];
    const float* cW    = (const float*)d_in[8];
    const float* cB    = (const float*)d_in[9];
    const float* w1    = (const float*)d_in[10];
    const float* b1    = (const float*)d_in[11];
    const float* w2a   = (const float*)d_in[12];
    const float* b2a   = (const float*)d_in[13];
    const float* w2b   = (const float*)d_in[14];
    const float* b2b   = (const float*)d_in[15];
    const float* sW    = (const float*)d_in[16];
    const float* sB    = (const float*)d_in[17];
    float* out = (float*)d_out;

    int pOff = out_size - 8 * 4096;  // spect first, probs second
    size_t smem = (size_t)18208 * sizeof(float);
    cudaFuncSetAttribute(fused_main, cudaFuncAttributeMaxDynamicSharedMemorySize,
                         (int)smem);

    zero_kernel<<<(pOff + 511) / 512, 512>>>(out, pOff);
    fused_main<<<1024, TH, smem>>>(vf, vmask, eoh, subs, cW, cB, w1, b1, w2a, b2a,
                                   w2b, b2b, sW, sB);
    softmax_kernel<<<8, 1024>>>(out + pOff);
    scatter_kernel<<<2048, 512>>>(midx, inten, out);
}

// round 17
// speedup vs baseline: 1.9350x; 1.0005x over previous
#include <cuda_runtime.h>
#include <cuda_bf16.h>

#define TH 256
#define MT 32
#define PITCH 36    // 32 + 4: conflict-free, 144B col stride (16B aligned)
#define SUBP 49     // raw subset tile stride (odd -> conflict-free)

// ---------------- device globals (no allocs allowed) ----------------
__device__ float g_scores[8 * 4096];
__device__ float g_probs[8 * 4096];

typedef unsigned long long ull;

// ---------------- f32x2 helpers (sm_103a packed fp32 FMA) ----------------
__device__ __forceinline__ ull pk2(float a, float b) {
    ull r;
    asm("mov.b64 %0, {%1,%2};" : "=l"(r) : "f"(a), "f"(b));
    return r;
}
__device__ __forceinline__ void upk2(ull v, float& a, float& b) {
    asm("mov.b64 {%0,%1}, %2;" : "=f"(a), "=f"(b) : "l"(v));
}
__device__ __forceinline__ ull fma2(ull a, ull b, ull c) {
    ull d;
    asm("fma.rn.f32x2 %0, %1, %2, %3;" : "=l"(d) : "l"(a), "l"(b), "l"(c));
    return d;
}

// ---------------- row-wise instance norm over 256 dims, 32 rows ----------------
// X layout: X[k*PITCH + r], k in [0,256), r in [0,32)
__device__ __forceinline__ void rownorm(float* X, float* red1, float* red2,
                                        float* rowM, float* rowR, int tid) {
    int r = tid & 31, part = tid >> 5;  // 8 parts x 32 cols
    float s1 = 0.f, s2 = 0.f;
    const float* base = X + (part * 32) * PITCH + r;
#pragma unroll
    for (int g = 0; g < 32; g++) {
        float v = base[g * PITCH];
        s1 += v;
        s2 += v * v;
    }
    red1[part * 32 + r] = s1;
    red2[part * 32 + r] = s2;
    __syncthreads();
    if (tid < 32) {
        float a = 0.f, bq = 0.f;
#pragma unroll
        for (int p = 0; p < 8; p++) {
            a += red1[p * 32 + tid];
            bq += red2[p * 32 + tid];
        }
        float m = a * (1.f / 256.f);
        float var = bq * (1.f / 256.f) - m * m;
        rowM[tid] = m;
        rowR[tid] = rsqrtf(var + 1e-5f);
    }
    __syncthreads();
#pragma unroll
    for (int i = 0; i < 32; i++) {
        int c = (tid >> 5) + i * 8, rr = tid & 31;
        float* p = X + c * PITCH + rr;
        *p = (*p - rowM[rr]) * rowR[rr];
    }
    __syncthreads();
}

// ---------------- tiled GEMM: Y[r][c] = act( sum_k X[k][r]*W[k][c] + b[c] ) ----------------
// src/dst col-major (PITCH); dst MAY ALIAS src (all reads complete before the
// epilogue stores: accumulation is register-resident, last tile ends with a
// barrier). W streamed coalesced from global [k][256], 8-row tiles,
// double-buffered. Thread map: tr=tid>>6 (rows 8tr..8tr+7), tc=tid&63.
// acc packed along ROW pairs -> X via uniform LDS.128 (reg-pair aliasing, no
// MOV), W scalar LDS.32 + dup.
// act: 0=relu+bias, 1=leaky(0.01)+bias, 2=scale by invs[row] (no bias/act)
__device__ __forceinline__ void mlp_gemm(const float* src, float* dst,
                                         const float* __restrict__ Wg,
                                         const float* __restrict__ bias,
                                         const float* __restrict__ invs,
                                         float* W0, float* W1, int Krows,
                                         int Ktiles, int act, int tid) {
    int tr = tid >> 6;  // 0..3
    int tc = tid & 63;
    ull acc[4][4];
#pragma unroll
    for (int i = 0; i < 4; i++)
#pragma unroll
        for (int c = 0; c < 4; c++) acc[i][c] = 0ull;

    const float4* W4 = (const float4*)Wg;
    float4 stg[2];

    // prologue: tile0 -> W0, prefetch tile1 -> regs
#pragma unroll
    for (int i = 0; i < 2; i++) {
        int f4i = tid + TH * i;
        int row = f4i >> 6;
        stg[i] = make_float4(0.f, 0.f, 0.f, 0.f);
        if (row < Krows) stg[i] = W4[row * 64 + (f4i & 63)];
    }
#pragma unroll
    for (int i = 0; i < 2; i++) ((float4*)W0)[tid + TH * i] = stg[i];
    if (Ktiles > 1) {
#pragma unroll
        for (int i = 0; i < 2; i++) {
            int f4i = tid + TH * i;
            int row = (f4i >> 6) + 8;
            stg[i] = make_float4(0.f, 0.f, 0.f, 0.f);
            if (row < Krows) stg[i] = W4[row * 64 + (f4i & 63)];
        }
    }
    __syncthreads();

    for (int kt = 0; kt < Ktiles; kt++) {
        float* cur = (kt & 1) ? W1 : W0;
        float* nxt = (kt & 1) ? W0 : W1;
        if (kt + 1 < Ktiles) {
#pragma unroll
            for (int i = 0; i < 2; i++) ((float4*)nxt)[tid + TH * i] = stg[i];
            if (kt + 2 < Ktiles) {
#pragma unroll
                for (int i = 0; i < 2; i++) {
                    int f4i = tid + TH * i;
                    int row = (f4i >> 6) + (kt + 2) * 8;
                    stg[i] = make_float4(0.f, 0.f, 0.f, 0.f);
                    if (row < Krows) stg[i] = W4[row * 64 + (f4i & 63)];
                }
            }
        }
        const float* xbase = src + (kt * 8) * PITCH + 8 * tr;
#pragma unroll
        for (int k = 0; k < 8; k++) {
            float4 xa = *(const float4*)(xbase + k * PITCH);      // uniform
            float4 xb = *(const float4*)(xbase + k * PITCH + 4);  // uniform
            ull xp0 = pk2(xa.x, xa.y);
            ull xp1 = pk2(xa.z, xa.w);
            ull xp2 = pk2(xb.x, xb.y);
            ull xp3 = pk2(xb.z, xb.w);
            const float* wr = cur + k * 256 + tc;
#pragma unroll
            for (int c = 0; c < 4; c++) {
                float w = wr[64 * c];
                ull wd = pk2(w, w);
                acc[0][c] = fma2(xp0, wd, acc[0][c]);
                acc[1][c] = fma2(xp1, wd, acc[1][c]);
                acc[2][c] = fma2(xp2, wd, acc[2][c]);
                acc[3][c] = fma2(xp3, wd, acc[3][c]);
            }
        }
        __syncthreads();
    }

    // epilogue (all reads done; safe even if dst aliases src)
#pragma unroll
    for (int c = 0; c < 4; c++) {
        int col = tc + 64 * c;
        float y[8];
        if (act == 2) {
#pragma unroll
            for (int rp = 0; rp < 4; rp++) {
                float lo, hi;
                upk2(acc[rp][c], lo, hi);
                y[2 * rp] = lo * invs[8 * tr + 2 * rp];
                y[2 * rp + 1] = hi * invs[8 * tr + 2 * rp + 1];
            }
        } else {
            float bb = __ldg(bias + col);
#pragma unroll
            for (int rp = 0; rp < 4; rp++) {
                float lo, hi;
                upk2(acc[rp][c], lo, hi);
                lo += bb;
                hi += bb;
                if (act == 0) {
                    lo = fmaxf(lo, 0.f);
                    hi = fmaxf(hi, 0.f);
                } else {
                    lo = (lo > 0.f) ? lo : 0.01f * lo;
                    hi = (hi > 0.f) ? hi : 0.01f * hi;
                }
                y[2 * rp] = lo;
                y[2 * rp + 1] = hi;
            }
        }
        float* dcol = dst + col * PITCH + 8 * tr;
        *(float4*)dcol = make_float4(y[0], y[1], y[2], y[3]);
        *(float4*)(dcol + 4) = make_float4(y[4], y[5], y[6], y[7]);
    }
    __syncthreads();
}

// ---------------- main fused kernel: one CTA = 32 subset rows of one batch ----------------
// Single activation buffer X (360 cols x PITCH), all GEMMs in-place -> 71 KB smem, occ 3.
__global__ void __launch_bounds__(TH, 3)
fused_main(const float* __restrict__ vf, const float* __restrict__ vmask,
           const float* __restrict__ eoh_g, const int* __restrict__ subs,
           const float* __restrict__ cW, const float* __restrict__ cB,
           const float* __restrict__ w1, const float* __restrict__ b1,
           const float* __restrict__ w2a, const float* __restrict__ b2a,
           const float* __restrict__ w2b, const float* __restrict__ b2b,
           const float* __restrict__ sW, const float* __restrict__ sB) {
    extern __shared__ float sm[];
    float* X = sm;                    // 360*36 = 12960 floats
    float* W0 = sm + 12960;           // 2048
    float* W1 = sm + 15008;           // 2048
    float* red1 = sm + 17056;         // 256
    float* red2 = sm + 17312;         // 256
    float* rowM = sm + 17568;         // 32
    float* rowR = sm + 17600;         // 32
    float* invs = sm + 17632;         // 32
    float* maskv = sm + 17664;        // 48
    float* eoh = sm + 17712;          // 240
    float* swbuf = sm + 17952;        // 256 -> total 18208 floats (72.8 KB)

    int tid = threadIdx.x;
    int b = blockIdx.x >> 7;           // 128 tiles per batch
    int s0 = (blockIdx.x & 127) * MT;

    float* SRAW = W0;  // alias: raw subset tile [32][SUBP] = 1568 <= 2048

    // ---- loads: raw subsets, mask, element one-hot, score weights ----
    for (int idx = tid; idx < MT * 48; idx += TH) {
        int r = idx / 48, a = idx - r * 48;
        SRAW[r * SUBP + a] = (float)subs[(b * 4096 + s0) * 48 + idx];
    }
    if (tid < 48) maskv[tid] = vmask[b * 48 + tid];
    if (tid < 240) eoh[tid] = eoh_g[b * 240 + tid];
    swbuf[tid] = sW[tid];
    __syncthreads();

    // ---- counts (160 thr), subset size (32 thr) ----
    if (tid < 160) {
        int r = tid / 5, e = tid - 5 * (tid / 5);
        float c = 0.f;
        for (int a = 0; a < 48; a++) c += SRAW[r * SUBP + a] * eoh[a * 5 + e];
        red2[tid] = c;
    } else if (tid < 192) {
        int r = tid - 160;
        float sz = 0.f;
        for (int a = 0; a < 48; a++) sz += SRAW[r * SUBP + a] * maskv[a];
        invs[r] = 1.f / (sz + 1e-4f);
    }
    __syncthreads();

    // ---- thermometer cols 0..99 ; SX = (s*m^2) k-major into X cols 308..355 ;
    //      zero K-pad cols 356..359 ----
    if (tid < 32) {
        int r = tid;
        float cnt[5];
#pragma unroll
        for (int e = 0; e < 5; e++) cnt[e] = red2[r * 5 + e];
#pragma unroll
        for (int e = 0; e < 5; e++)
            for (int j = 0; j < 20; j++)
                X[(e * 20 + j) * PITCH + r] = ((float)j < cnt[e]) ? 1.f : 0.f;
    }
    for (int idx = tid; idx < 48 * 32; idx += TH) {
        int a = idx >> 5, r = idx & 31;
        float m = maskv[a];
        X[(308 + a) * PITCH + r] = SRAW[r * SUBP + a] * m * m;
    }
    if (tid >= 128 && tid < 256) {  // zero K-pad cols 356..359
        int rr = (tid - 128) & 31, col = 356 + ((tid - 128) >> 5);
        X[col * PITCH + rr] = 0.f;
    }
    __syncthreads();

    // ---- stage A as GEMM: meanfeat = (SX^T @ vf_b) * invs -> X cols 100..355 ----
    // (src cols 308..355 are re-read fully before the epilogue overwrites them)
    mlp_gemm(X + 308 * PITCH, X + 100 * PITCH, vf + b * 48 * 256, 0, invs, W0, W1,
             48, 6, 2, tid);

    rownorm(X + 100 * PITCH, red1, red2, rowM, rowR, tid);          // subset_weighted_norm
    mlp_gemm(X, X, cW, cB, 0, W0, W1, 356, 45, 0, tid);             // combine + relu (in-place)
    rownorm(X, red1, red2, rowM, rowR, tid);                        // norm_post_combine
    mlp_gemm(X, X, w1, b1, 0, W0, W1, 256, 32, 0, tid);             // l1 + relu
    mlp_gemm(X, X, w2a, b2a, 0, W0, W1, 256, 32, 1, tid);           // l2a + leaky
    mlp_gemm(X, X, w2b, b2b, 0, W0, W1, 256, 32, 0, tid);           // l2b: leaky+relu == relu

    // ---- fused norm_pre_score + score head: score = rs*(Sxw - m*Sw) + b ----
    {
        float* red3 = W0;        // W tiles free now
        float* red4 = W0 + 256;
        int r = tid & 31, part = tid >> 5;
        const float* base = X + (part * 32) * PITCH + r;
        float s1 = 0.f, s2 = 0.f, sxw = 0.f, swp = 0.f;
#pragma unroll
        for (int g = 0; g < 32; g++) {
            float v = base[g * PITCH];
            float w = swbuf[part * 32 + g];
            s1 += v;
            s2 += v * v;
            sxw += v * w;
            swp += w;
        }
        red1[part * 32 + r] = s1;
        red2[part * 32 + r] = s2;
        red3[part * 32 + r] = sxw;
        red4[part * 32 + r] = swp;
        __syncthreads();
        if (tid < 32) {
            float a = 0.f, bq = 0.f, xw = 0.f, sw = 0.f;
#pragma unroll
            for (int p = 0; p < 8; p++) {
                a += red1[p * 32 + tid];
                bq += red2[p * 32 + tid];
                xw += red3[p * 32 + tid];
                sw += red4[p * 32 + tid];
            }
            float m = a * (1.f / 256.f);
            float var = bq * (1.f / 256.f) - m * m;
            float rs = rsqrtf(var + 1e-5f);
            g_scores[b * 4096 + s0 + tid] = rs * (xw - m * sw) + __ldg(sB);
        }
    }
}

// ---------------- per-batch softmax over 4096 scores ----------------
__global__ void softmax_kernel(float* __restrict__ probs_out) {
    __shared__ float sbuf[32];
    __shared__ float sval;
    int b = blockIdx.x, t = threadIdx.x, lane = t & 31, wid = t >> 5;
    const float* sc = g_scores + b * 4096;
    float v0 = sc[t], v1 = sc[t + 1024], v2 = sc[t + 2048], v3 = sc[t + 3072];
    float mx = fmaxf(fmaxf(v0, v1), fmaxf(v2, v3));
#pragma unroll
    for (int o = 16; o; o >>= 1) mx = fmaxf(mx, __shfl_xor_sync(0xffffffffu, mx, o));
    if (lane == 0) sbuf[wid] = mx;
    __syncthreads();
    if (t < 32) {
        float m = sbuf[t];
#pragma unroll
        for (int o = 16; o; o >>= 1) m = fmaxf(m, __shfl_xor_sync(0xffffffffu, m, o));
        if (t == 0) sval = m;
    }
    __syncthreads();
    mx = sval;
    float e0 = expf(v0 - mx), e1 = expf(v1 - mx), e2 = expf(v2 - mx), e3 = expf(v3 - mx);
    float sum = e0 + e1 + e2 + e3;
#pragma unroll
    for (int o = 16; o; o >>= 1) sum += __shfl_xor_sync(0xffffffffu, sum, o);
    __syncthreads();
    if (lane == 0) sbuf[wid] = sum;
    __syncthreads();
    if (t < 32) {
        float s = sbuf[t];
#pragma unroll
        for (int o = 16; o; o >>= 1) s += __shfl_xor_sync(0xffffffffu, s, o);
        if (t == 0) sval = s;
    }
    __syncthreads();
    float inv = 1.f / sval;
    float p0 = e0 * inv, p1 = e1 * inv, p2 = e2 * inv, p3 = e3 * inv;
    probs_out[b * 4096 + t] = p0;
    probs_out[b * 4096 + t + 1024] = p1;
    probs_out[b * 4096 + t + 2048] = p2;
    probs_out[b * 4096 + t + 3072] = p3;
    g_probs[b * 4096 + t] = p0;
    g_probs[b * 4096 + t + 1024] = p1;
    g_probs[b * 4096 + t + 2048] = p2;
    g_probs[b * 4096 + t + 3072] = p3;
}

// ---------------- zero + scatter into spectral bins ----------------
__global__ void zero_kernel(float* __restrict__ p, int n) {
    int idx = blockIdx.x * blockDim.x + threadIdx.x;
    if (idx < n) p[idx] = 0.f;
}

__global__ void scatter_kernel(const int* __restrict__ midx,
                               const float* __restrict__ inten,
                               float* __restrict__ spect) {
    int idx = blockIdx.x * blockDim.x + threadIdx.x;
    if (idx >= 8 * 4096 * 32) return;
    int b = idx >> 17;              // 4096*32 = 131072
    int s = (idx >> 5) & 4095;
    float w = inten[idx] * g_probs[b * 4096 + s];
    atomicAdd(spect + b * 65536 + midx[idx], w);
}

// ---------------- launch ----------------
extern "C" void kernel_launch(void* const* d_in, const int* in_sizes, int n_in,
                              void* d_out, int out_size) {
    const float* vf    = (const float*)d_in[0];
    const float* vmask = (const float*)d_in[1];
    const float* eoh   = (const float*)d_in[2];
    const int*   subs  = (const int*)d_in[4];
    const int*   midx  = (const int*)d_in[6];
    const float* inten = (const float*)d_in[7];
    const float* cW    = (const float*)d_in[8];
    const float* cB    = (const float*)d_in[9];
    const float* w1    = (const float*)d_in[10];
    const float* b1    = (const float*)d_in[11];
    const float* w2a   = (const float*)d_in[12];
    const float* b2a   = (const float*)d_in[13];
    const float* w2b   = (const float*)d_in[14];
    const float* b2b   = (const float*)d_in[15];
    const float* sW    = (const float*)d_in[16];
    const float* sB    = (const float*)d_in[17];
    float* out = (float*)d_out;

    int pOff = out_size - 8 * 4096;  // spect first, probs second
    size_t smem = (size_t)18208 * sizeof(float);
    cudaFuncSetAttribute(fused_main, cudaFuncAttributeMaxDynamicSharedMemorySize,
                         (int)smem);

    zero_kernel<<<(pOff + 511) / 512, 512>>>(out, pOff);
    fused_main<<<1024, TH, smem>>>(vf, vmask, eoh, subs, cW, cB, w1, b1, w2a, b2a,
                                   w2b, b2b, sW, sB);
    softmax_kernel<<<8, 1024>>>(out + pOff);
    scatter_kernel<<<2048, 512>>>(midx, inten, out);
}